// round 8
// baseline (speedup 1.0000x reference)
#include <cuda_runtime.h>
#include <cuda_bf16.h>
#include <cstdint>

// NCE loss (training branch, size_average=True).
// N=4096, E=1024, V=50257, K=25.
// Persistent kernel: 1184 CTAs (8/SM x 148 SMs) grid-striding over rows.
// Weight gather via __ldcg (L2-only, no L1 line allocation -- gather has no
// L1 reuse). x[n] triple-buffered in SMEM via cp.async: one barrier per row.

#define THREADS 256
#define NWARP   8
#define GRID    1184          // 148 SMs * 8 CTAs
#define XBUF    3

__device__ __forceinline__ void cp16(uint32_t dst, const void* src) {
    asm volatile("cp.async.cg.shared.global [%0], [%1], 16;\n" :: "r"(dst), "l"(src));
}
__device__ __forceinline__ void cp_commit() {
    asm volatile("cp.async.commit_group;\n" ::: "memory");
}

__global__ __launch_bounds__(THREADS, 8)
void nce_main(const float* __restrict__ x,
              const int*   __restrict__ target,
              const int*   __restrict__ noise_idx,
              const float* __restrict__ weight,
              const float* __restrict__ bias,
              const float* __restrict__ noise,
              float* __restrict__ out,
              int N, int E, int K)
{
    const int tid  = threadIdx.x;
    const int lane = tid & 31;
    const int wid  = tid >> 5;
    const int nk   = K + 1;                // 26

    __shared__ float4 xs[XBUF][256];       // x row ring (3 x 4KB)
    __shared__ float  wloss[NWARP];

    uint32_t xs_addr[XBUF];
    {
        uint32_t base;
        asm("{ .reg .u64 t; cvta.to.shared.u64 t, %1; cvt.u32.u64 %0, t; }"
            : "=r"(base) : "l"(&xs[0][0]));
        #pragma unroll
        for (int b = 0; b < XBUF; b++) xs_addr[b] = base + b * 4096 + tid * 16;
    }

    // Prime slot 0 with the first row's x
    const int n0 = blockIdx.x;
    if (n0 < N) {
        cp16(xs_addr[0], (const char*)(x + (size_t)n0 * E) + tid * 16);
        cp_commit();
    }

    float loss = 0.0f;                     // lane-0-held, accumulated across rows
    int buf = 0;

    for (int n = n0; n < N; n += GRID) {
        // Stream the NEXT row's x into the next ring slot (reuse distance 3:
        // the slot being overwritten was fully consumed >=2 barriers ago).
        const int n_next = n + GRID;
        const int nbuf   = (buf + 1 == XBUF) ? 0 : buf + 1;
        if (n_next < N) {
            cp16(xs_addr[nbuf], (const char*)(x + (size_t)n_next * E) + tid * 16);
            cp_commit();
            asm volatile("cp.async.wait_group 1;\n" ::: "memory");  // this row done
        } else {
            asm volatile("cp.async.wait_group 0;\n" ::: "memory");
        }
        __syncthreads();                   // single barrier per row

        const float4* xb = xs[buf];

        for (int k = wid; k < nk; k += NWARP) {
            const int idx = (k == 0) ? target[n] : noise_idx[n * K + (k - 1)];
            const float4* wrow = reinterpret_cast<const float4*>(weight + (size_t)idx * E);

            float s = 0.0f;
            #pragma unroll
            for (int j = 0; j < 8; j++) {   // 8 independent LDG.128.CG per lane
                const float4 wv = __ldcg(&wrow[lane + 32 * j]);
                const float4 xv = xb[lane + 32 * j];
                s += wv.x * xv.x + wv.y * xv.y + wv.z * xv.z + wv.w * xv.w;
            }
            #pragma unroll
            for (int o = 16; o; o >>= 1)
                s += __shfl_xor_sync(0xffffffffu, s, o);

            if (lane == 0) {
                const float logit = s + __ldg(&bias[idx]);
                const float p     = __expf(logit - 9.0f);
                const float kpn   = 25.0f * __ldg(&noise[idx]);
                const float num   = (k == 0) ? p : kpn;
                loss += __logf(num / (p + kpn));
            }
        }
        buf = nbuf;
    }

    if (lane == 0) wloss[wid] = loss;
    __syncthreads();
    if (tid == 0) {
        float t = 0.0f;
        #pragma unroll
        for (int w = 0; w < NWARP; w++) t += wloss[w];
        atomicAdd(out, -t / (float)N);     // one atomic per CTA
    }
}

extern "C" void kernel_launch(void* const* d_in, const int* in_sizes, int n_in,
                              void* d_out, int out_size)
{
    const float* x         = (const float*)d_in[0];
    const int*   target    = (const int*)  d_in[1];
    const int*   noise_idx = (const int*)  d_in[2];
    const float* weight    = (const float*)d_in[3];
    const float* bias      = (const float*)d_in[4];
    const float* noise     = (const float*)d_in[5];

    const int N = in_sizes[1];            // 4096
    const int E = in_sizes[0] / N;        // 1024
    const int K = in_sizes[2] / N;        // 25

    cudaMemsetAsync(d_out, 0, sizeof(float));
    nce_main<<<GRID, THREADS>>>(x, target, noise_idx, weight, bias, noise,
                                (float*)d_out, N, E, K);
}